// round 17
// baseline (speedup 1.0000x reference)
#include <cuda_runtime.h>

// LSTM: B=4096, T=512, I=3, H=32, C=3
// R16: j-split teams. 2 warps/block, NB=4 batches/block (1024 blocks, 2048 warps).
//      warp0 accumulates all 4 gate-pairs over j in [0,16), warp1 over [16,32):
//      per warp-step 32 LDS.128 + 128 fma2 (R10's MIO:FMA ratio preserved).
//      Symmetric partial-sum exchange; each warp finalizes acts for 2 batches.
//      Doubles resident warps/SMSP at constant per-warp MIO ratio.

#define FULL_MASK 0xffffffffu
typedef unsigned long long ull;

constexpr int B_DIM  = 4096;
constexpr int T_DIM  = 512;
constexpr int H_DIM  = 32;
constexpr int NB     = 4;     // batches per block
constexpr int NTHREADS = 64;  // 2 warps
constexpr int CHUNK  = 32;    // timesteps per staged chunk
constexpr int NCHUNK = T_DIM / CHUNK;  // 16
constexpr int JH     = H_DIM / 2;      // 16 j per warp

__device__ __forceinline__ float tanh_fast(float x) {
    float y;
    asm("tanh.approx.f32 %0, %1;" : "=f"(y) : "f"(x));
    return y;
}
__device__ __forceinline__ ull pack2(float lo, float hi) {
    ull r;
    asm("mov.b64 %0, {%1, %2};"
        : "=l"(r) : "r"(__float_as_uint(lo)), "r"(__float_as_uint(hi)));
    return r;
}
__device__ __forceinline__ void unpack2(ull v, float& lo, float& hi) {
    unsigned int a, b;
    asm("mov.b64 {%0, %1}, %2;" : "=r"(a), "=r"(b) : "l"(v));
    lo = __uint_as_float(a);
    hi = __uint_as_float(b);
}
__device__ __forceinline__ void fma2(ull& acc, ull a, ull b) {
    asm("fma.rn.f32x2 %0, %1, %2, %0;" : "+l"(acc) : "l"(a), "l"(b));
}
__device__ __forceinline__ ull fma2o(ull a, ull b, ull c) {
    ull d;
    asm("fma.rn.f32x2 %0, %1, %2, %3;" : "=l"(d) : "l"(a), "l"(b), "l"(c));
    return d;
}
__device__ __forceinline__ ull add2(ull a, ull b) {
    ull d;
    asm("add.rn.f32x2 %0, %1, %2;" : "=l"(d) : "l"(a), "l"(b));
    return d;
}

// activation + cell update; pre-acts for i,f,o pre-scaled by 0.5
__device__ __forceinline__ void do_act(ull pre01, ull pre23, float& c, float& h) {
    float pi, pf, pg, po;
    unpack2(pre01, pi, pf);
    unpack2(pre23, pg, po);
    float ig = fmaf(0.5f, tanh_fast(pi), 0.5f);
    float fg = fmaf(0.5f, tanh_fast(pf), 0.5f);
    float gg = tanh_fast(pg);
    float og = fmaf(0.5f, tanh_fast(po), 0.5f);
    c = fmaf(fg, c, ig * gg);
    h = og * tanh_fast(c);
}

__global__ void __launch_bounds__(NTHREADS, 7)
lstm_fused_kernel(const float* __restrict__ x,      // (B,T,3)
                  const float* __restrict__ W_ih,   // (128,3)
                  const float* __restrict__ W_hh,   // (128,32)
                  const float* __restrict__ b_ih,   // (128,)
                  const float* __restrict__ b_hh,   // (128,)
                  const float* __restrict__ W_fc,   // (3,32)
                  const float* __restrict__ b_fc,   // (3,)
                  float* __restrict__ out)          // (B,3)
{
    // x chunk: 4 batches * 24 float4 (1.5 KB), plain layout (R10 style)
    __shared__ float4 sx4[NB * (CHUNK * 3 / 4)];
    // duplicated h, double-buffered: shb[pb][j][0]={h0,h0,h1,h1}, [1]={h2,h2,h3,h3}
    __shared__ float4 shb[2][H_DIM][2];
    // partial-acc exchange: sex[srcwarp][m][lane] = {acc01, acc23} of non-owned batch m
    __shared__ ulonglong2 sex[2][2][32];

    const int tid  = threadIdx.x;
    const int lane = tid & 31;
    const int warp = tid >> 5;
    const int b0   = blockIdx.x * NB;
    const int j0   = warp * JH;        // this warp's j-half
    const int own0 = warp * 2;         // first owned batch (0 or 2)

    // ---- W_hh columns j0..j0+15, all 4 gate rows, packed + scaled ----
    ull w01[JH], w23[JH];
    {
        const float* r0 = W_hh + (0 * 32 + lane) * H_DIM + j0;
        const float* r1 = W_hh + (1 * 32 + lane) * H_DIM + j0;
        const float* r2 = W_hh + (2 * 32 + lane) * H_DIM + j0;
        const float* r3 = W_hh + (3 * 32 + lane) * H_DIM + j0;
#pragma unroll
        for (int jj = 0; jj < JH; jj++) {
            w01[jj] = pack2(r0[jj] * 0.5f, r1[jj] * 0.5f);
            w23[jj] = pack2(r2[jj],        r3[jj] * 0.5f);
        }
    }

    // ---- input weights + combined bias, packed per gate pair (both warps) ----
    ull wp01[3], wp23[3];
#pragma unroll
    for (int k = 0; k < 3; k++) {
        wp01[k] = pack2(W_ih[(0 * 32 + lane) * 3 + k] * 0.5f,
                        W_ih[(1 * 32 + lane) * 3 + k] * 0.5f);
        wp23[k] = pack2(W_ih[(2 * 32 + lane) * 3 + k],
                        W_ih[(3 * 32 + lane) * 3 + k] * 0.5f);
    }
    const ull bias01 = pack2((b_ih[lane]      + b_hh[lane])      * 0.5f,
                             (b_ih[32 + lane] + b_hh[32 + lane]) * 0.5f);
    const ull bias23 = pack2((b_ih[64 + lane] + b_hh[64 + lane]),
                             (b_ih[96 + lane] + b_hh[96 + lane]) * 0.5f);

    // init h buffer 0 (warp0 slot 0 = b0,b1; warp1 slot 1 = b2,b3)
    shb[0][lane][warp] = make_float4(0.f, 0.f, 0.f, 0.f);
    __syncthreads();

    // c/h state for the 2 owned batches
    float c0 = 0.f, c1 = 0.f, h0 = 0.f, h1 = 0.f;

    const float* sxf = reinterpret_cast<const float*>(sx4);
    const float4* xv = reinterpret_cast<const float4*>(x);
    const ull zero2 = pack2(0.f, 0.f);
    int pb = 0;

    for (int k = 0; k < NCHUNK; k++) {
        // ---- stage x chunk: 96 float4, 64 threads ----
#pragma unroll
        for (int it = 0; it < 2; it++) {
            int idx = tid + it * 64;
            if (idx < 96) {
                int n = idx / 24, rem = idx % 24;
                sx4[idx] = xv[(size_t)(b0 + n) * (T_DIM * 3 / 4) + k * 24 + rem];
            }
        }
        __syncthreads();

#pragma unroll 1
        for (int tt = 0; tt < CHUNK; tt++) {
            // ---- accs: owned batches init with input projection, others zero ----
            ull a01[NB], a23[NB];
#pragma unroll
            for (int m = 0; m < 2; m++) {
                int n = own0 + m;
                float x0 = sxf[n * 96 + tt * 3 + 0];
                float x1 = sxf[n * 96 + tt * 3 + 1];
                float x2 = sxf[n * 96 + tt * 3 + 2];
                ull p01 = fma2o(wp01[0], pack2(x0, x0), bias01);
                ull p23 = fma2o(wp23[0], pack2(x0, x0), bias23);
                p01 = fma2o(wp01[1], pack2(x1, x1), p01);
                p23 = fma2o(wp23[1], pack2(x1, x1), p23);
                p01 = fma2o(wp01[2], pack2(x2, x2), p01);
                p23 = fma2o(wp23[2], pack2(x2, x2), p23);
                a01[n] = p01;
                a23[n] = p23;
            }
#pragma unroll
            for (int m = 0; m < 2; m++) {
                int n = (own0 ^ 2) + m;   // non-owned batches
                a01[n] = zero2;
                a23[n] = zero2;
            }

            // ---- partial recurrent matvec over this warp's j-half ----
            {
                const ulonglong2* hb =
                    reinterpret_cast<const ulonglong2*>(&shb[pb][j0][0]);
#pragma unroll
                for (int jj = 0; jj < JH; jj++) {
                    ulonglong2 ha = hb[jj * 2 + 0];  // {h0,h0} {h1,h1}
                    ulonglong2 hc = hb[jj * 2 + 1];  // {h2,h2} {h3,h3}
                    fma2(a01[0], w01[jj], ha.x); fma2(a23[0], w23[jj], ha.x);
                    fma2(a01[1], w01[jj], ha.y); fma2(a23[1], w23[jj], ha.y);
                    fma2(a01[2], w01[jj], hc.x); fma2(a23[2], w23[jj], hc.x);
                    fma2(a01[3], w01[jj], hc.y); fma2(a23[3], w23[jj], hc.y);
                }
            }

            // ---- exchange partials for non-owned batches ----
            {
                int nn = own0 ^ 2;
                ulonglong2 p0; p0.x = a01[nn];     p0.y = a23[nn];
                ulonglong2 p1; p1.x = a01[nn + 1]; p1.y = a23[nn + 1];
                sex[warp][0][lane] = p0;
                sex[warp][1][lane] = p1;
            }
            __syncthreads();

            // ---- finalize owned batches: own + partner partial, then act ----
            {
                ulonglong2 q0 = sex[warp ^ 1][0][lane];  // partner partial, owned batch 0
                ulonglong2 q1 = sex[warp ^ 1][1][lane];  // owned batch 1
                ull t01 = add2(a01[own0], q0.x);
                ull t23 = add2(a23[own0], q0.y);
                do_act(t01, t23, c0, h0);
                ull u01 = add2(a01[own0 + 1], q1.x);
                ull u23 = add2(a23[own0 + 1], q1.y);
                do_act(u01, u23, c1, h1);
            }

            // ---- publish duplicated h for owned batches ----
            shb[pb ^ 1][lane][warp] = make_float4(h0, h0, h1, h1);
            __syncthreads();
            pb ^= 1;
        }
    }

    // ---- final FC for the 2 owned batches ----
    const float wfc0 = W_fc[0 * H_DIM + lane];
    const float wfc1 = W_fc[1 * H_DIM + lane];
    const float wfc2 = W_fc[2 * H_DIM + lane];
#pragma unroll
    for (int m = 0; m < 2; m++) {
        float hn = (m == 0) ? h0 : h1;
        float v0 = hn * wfc0;
        float v1 = hn * wfc1;
        float v2 = hn * wfc2;
#pragma unroll
        for (int off = 16; off > 0; off >>= 1) {
            v0 += __shfl_xor_sync(FULL_MASK, v0, off);
            v1 += __shfl_xor_sync(FULL_MASK, v1, off);
            v2 += __shfl_xor_sync(FULL_MASK, v2, off);
        }
        if (lane == 0) {
            int b = b0 + own0 + m;
            out[b * 3 + 0] = v0 + b_fc[0];
            out[b * 3 + 1] = v1 + b_fc[1];
            out[b * 3 + 2] = v2 + b_fc[2];
        }
    }
}

extern "C" void kernel_launch(void* const* d_in, const int* in_sizes, int n_in,
                              void* d_out, int out_size) {
    const float* x    = (const float*)d_in[0];
    const float* W_ih = (const float*)d_in[1];
    const float* W_hh = (const float*)d_in[2];
    const float* b_ih = (const float*)d_in[3];
    const float* b_hh = (const float*)d_in[4];
    const float* W_fc = (const float*)d_in[5];
    const float* b_fc = (const float*)d_in[6];
    float* out = (float*)d_out;

    const int grid = B_DIM / NB;  // 1024 two-warp blocks
    lstm_fused_kernel<<<grid, NTHREADS>>>(x, W_ih, W_hh, b_ih, b_hh, W_fc, b_fc, out);
}